// round 6
// baseline (speedup 1.0000x reference)
#include <cuda_runtime.h>

#define FULLMASK 0xffffffffu

// ---------------------------------------------------------------------------
// State: amplitude index i (8 bits) = (r << 5) | lane. wire w <-> bit (7-w).
// Bits 0..4 lane, 5..7 register. Scalar state re[8], im[8] per lane.
// Per (layer,node) the 1q chain RY(theta)*ROT*G2_1q is FUSED into one 2x2
// matrix (uniform part in setup; per-sample RY folded at runtime, warp-
// uniform scalar work) -> at most ONE lane exchange per node.
// No f32x2 packing: R5 showed pack/unpack MOVs blow up the alu pipe.
// ---------------------------------------------------------------------------

template<int B>
__device__ __forceinline__ float lshfl(float v) {
    return __shfl_xor_sync(FULLMASK, v, 1 << B);
}

// ------------------------- fused 1q applies ---------------------------------

// Real 2x2 [u00,u01;u10,u11]
template<int B>
__device__ __forceinline__ void ap_real(float re[8], float im[8], int lane,
                                        float u00, float u01, float u10, float u11) {
    if constexpr (B >= 5) {
        constexpr int M = 1 << (B - 5);
#pragma unroll
        for (int r = 0; r < 8; r++) {
            if ((r & M) == 0) {
                int r1 = r | M;
                float a0 = re[r], a1 = re[r1];
                re[r]  = u00 * a0 + u01 * a1;
                re[r1] = u10 * a0 + u11 * a1;
                a0 = im[r]; a1 = im[r1];
                im[r]  = u00 * a0 + u01 * a1;
                im[r1] = u10 * a0 + u11 * a1;
            }
        }
    } else {
        int bit = (lane >> B) & 1;
        float u = bit ? u11 : u00;     // hoisted: 2 SELs per gate
        float v = bit ? u10 : u01;
#pragma unroll
        for (int r = 0; r < 8; r++) {
            float pr = lshfl<B>(re[r]);
            float pi = lshfl<B>(im[r]);
            re[r] = u * re[r] + v * pr;
            im[r] = u * im[r] + v * pi;
        }
    }
}

// Complex 2x2, entries (ur+i*ui) etc.
template<int B>
__device__ __forceinline__ void ap_cplx(float re[8], float im[8], int lane,
                                        float m00r, float m00i, float m01r, float m01i,
                                        float m10r, float m10i, float m11r, float m11i) {
    if constexpr (B >= 5) {
        constexpr int M = 1 << (B - 5);
#pragma unroll
        for (int r = 0; r < 8; r++) {
            if ((r & M) == 0) {
                int r1 = r | M;
                float r0 = re[r], i0 = im[r], r1v = re[r1], i1 = im[r1];
                re[r]  = m00r * r0 - m00i * i0 + m01r * r1v - m01i * i1;
                im[r]  = m00r * i0 + m00i * r0 + m01r * i1  + m01i * r1v;
                re[r1] = m10r * r0 - m10i * i0 + m11r * r1v - m11i * i1;
                im[r1] = m10r * i0 + m10i * r0 + m11r * i1  + m11i * r1v;
            }
        }
    } else {
        int bit = (lane >> B) & 1;
        float ur = bit ? m11r : m00r, ui = bit ? m11i : m00i;
        float vr = bit ? m10r : m01r, vi = bit ? m10i : m01i;
#pragma unroll
        for (int r = 0; r < 8; r++) {
            float pr = lshfl<B>(re[r]);
            float pi = lshfl<B>(im[r]);
            float ar = re[r], ai = im[r];
            re[r] = ur * ar - ui * ai + vr * pr - vi * pi;
            im[r] = ur * ai + ui * ar + vr * pi + vi * pr;
        }
    }
}

// Diagonal complex: a' = d(bit) * a — zero shuffles.
template<int B>
__device__ __forceinline__ void ap_diag(float re[8], float im[8], int lane,
                                        float d0r, float d0i, float d1r, float d1i) {
    if constexpr (B >= 5) {
        constexpr int M = 1 << (B - 5);
#pragma unroll
        for (int r = 0; r < 8; r++) {
            float dr = (r & M) ? d1r : d0r;   // compile-time pick
            float di = (r & M) ? d1i : d0i;
            float ar = re[r], ai = im[r];
            re[r] = dr * ar - di * ai;
            im[r] = dr * ai + di * ar;
        }
    } else {
        int bit = (lane >> B) & 1;
        float dr = bit ? d1r : d0r;
        float di = bit ? d1i : d0i;
#pragma unroll
        for (int r = 0; r < 8; r++) {
            float ar = re[r], ai = im[r];
            re[r] = dr * ar - di * ai;
            im[r] = dr * ai + di * ar;
        }
    }
}

// ------------------------- multi-qubit gates --------------------------------

// Controlled-X: flip bit T where all CM bits set. CM==0 -> plain X.
template<int T, int CM>
__device__ __forceinline__ void g_cx(float re[8], float im[8], int lane) {
    constexpr int CML = CM & 31;
    constexpr int CMR = (CM >> 5) & 7;
    bool lp = ((lane & CML) == CML);
    if constexpr (T < 5) {
#pragma unroll
        for (int r = 0; r < 8; r++) {
            if ((r & CMR) == CMR) {
                float pr = lshfl<T>(re[r]);
                float pi = lshfl<T>(im[r]);
                if constexpr (CML == 0) { re[r] = pr; im[r] = pi; }
                else {
                    re[r] = lp ? pr : re[r];
                    im[r] = lp ? pi : im[r];
                }
            }
        }
    } else {
        constexpr int MT = 1 << (T - 5);
#pragma unroll
        for (int r = 0; r < 8; r++) {
            if (((r & CMR) == CMR) && !(r & MT)) {   // each pair once
                int r1 = r | MT;
                if constexpr (CML == 0) {
                    float t = re[r]; re[r] = re[r1]; re[r1] = t;
                    t = im[r]; im[r] = im[r1]; im[r1] = t;
                } else {
                    float a0 = re[r], a1 = re[r1];
                    re[r] = lp ? a1 : a0;  re[r1] = lp ? a0 : a1;
                    a0 = im[r]; a1 = im[r1];
                    im[r] = lp ? a1 : a0;  im[r1] = lp ? a0 : a1;
                }
            }
        }
    }
}

// CZ on bits BA, BB
template<int BA, int BB>
__device__ __forceinline__ void g_cz(float re[8], float im[8], int lane) {
    bool lp = true;
    if constexpr (BA < 5) lp = lp && (((lane >> BA) & 1) != 0);
    if constexpr (BB < 5) lp = lp && (((lane >> BB) & 1) != 0);
    float sg = lp ? -1.f : 1.f;
#pragma unroll
    for (int r = 0; r < 8; r++) {
        bool rp = true;
        if (BA >= 5) rp = rp && (((r >> (BA - 5)) & 1) != 0);
        if (BB >= 5) rp = rp && (((r >> (BB - 5)) & 1) != 0);
        if (rp) { re[r] *= sg; im[r] *= sg; }
    }
}

template<int A, int Bb, int C>
__device__ __forceinline__ constexpr bool cswap_possible(int r) {
    bool possible = true;
    if (C >= 5 && !((r >> (C - 5)) & 1)) possible = false;
    if (A >= 5 && Bb >= 5 &&
        (((r >> (A - 5)) & 1) == ((r >> (Bb - 5)) & 1))) possible = false;
    return possible;
}

// CSWAP: control C; swap bits A,Bb where they differ. GATHER-THEN-UPDATE.
template<int A, int Bb, int C>
__device__ __forceinline__ void g_cswap(float re[8], float im[8], int lane) {
    constexpr int M  = (1 << A) | (1 << Bb);
    constexpr int ML = M & 31;
    constexpr int MR = (M >> 5) & 7;
    float pre[8], pim[8];
#pragma unroll
    for (int r = 0; r < 8; r++) {
        if (cswap_possible<A, Bb, C>(r)) {
            float vr = re[r ^ MR], vi = im[r ^ MR];
            if constexpr (ML != 0) {
                vr = __shfl_xor_sync(FULLMASK, vr, ML);
                vi = __shfl_xor_sync(FULLMASK, vi, ML);
            }
            pre[r] = vr; pim[r] = vi;
        }
    }
    bool lctl = true;
    if constexpr (C < 5) lctl = (((lane >> C) & 1) != 0);
#pragma unroll
    for (int r = 0; r < 8; r++) {
        if (cswap_possible<A, Bb, C>(r)) {
            int ba = (A  < 5) ? ((lane >> A)  & 1) : ((r >> (A  - 5)) & 1);
            int bb = (Bb < 5) ? ((lane >> Bb) & 1) : ((r >> (Bb - 5)) & 1);
            bool ctl = lctl;
            if (C >= 5) ctl = (((r >> (C - 5)) & 1) != 0);
            bool sw = ctl && (ba != bb);
            re[r] = sw ? pre[r] : re[r];
            im[r] = sw ? pim[r] : im[r];
        }
    }
}

// ---------------------------------------------------------------------------
// Setup: per (layer,node) precompute A = G2_1q * ROT (complex 2x2), classify.
// code bits: 0 = has_ry, [1:3) = atype (0 none,1 diag,2 real,3 cplx),
//            [3:7) = multi-q gate (0 or 5..8).
// g_mat[2i] = (A00r,A00i,A01r,A01i), g_mat[2i+1] = (A10r,A10i,A11r,A11i).
// ---------------------------------------------------------------------------
__device__ float4 g_mat[96];
__device__ int g_code[48];

struct C2 { float re, im; };
__device__ __forceinline__ C2 cxm(C2 a, C2 b) {
    C2 o; o.re = a.re * b.re - a.im * b.im; o.im = a.re * b.im + a.im * b.re; return o;
}
__device__ __forceinline__ C2 cxa(C2 a, C2 b) { C2 o; o.re = a.re + b.re; o.im = a.im + b.im; return o; }

__global__ void setup_kernel(const float* __restrict__ qp,
                             const int* __restrict__ dry,
                             const int* __restrict__ drot,
                             const int* __restrict__ dg2) {
    int i = threadIdx.x;
    if (i >= 48) return;
    int layer = i >> 3, node = i & 7;
    int di = layer * 4 + (node & 3);
    float s, c;
    __sincosf(0.5f * qp[i], &s, &c);

    C2 A[2][2] = {{{1.f,0.f},{0.f,0.f}},{{0.f,0.f},{1.f,0.f}}};
    bool haveA = false;
    int rot = drot[di];
    if (rot == 0) {        // RX
        A[0][0] = {c,0.f}; A[0][1] = {0.f,-s}; A[1][0] = {0.f,-s}; A[1][1] = {c,0.f};
        haveA = true;
    } else if (rot == 1) { // RY
        A[0][0] = {c,0.f}; A[0][1] = {-s,0.f}; A[1][0] = {s,0.f};  A[1][1] = {c,0.f};
        haveA = true;
    } else if (rot == 2) { // RZ
        A[0][0] = {c,-s};  A[0][1] = {0.f,0.f}; A[1][0] = {0.f,0.f}; A[1][1] = {c,s};
        haveA = true;
    }
    int g2 = dg2[di];
    if (g2 >= 1 && g2 <= 4) {
        const float rh = 0.70710678118654752440f;
        C2 G[2][2];
        if (g2 == 1) {
            G[0][0] = {rh,0.f}; G[0][1] = {rh,0.f}; G[1][0] = {rh,0.f}; G[1][1] = {-rh,0.f};
        } else if (g2 == 2) {
            G[0][0] = {0.f,0.f}; G[0][1] = {1.f,0.f}; G[1][0] = {1.f,0.f}; G[1][1] = {0.f,0.f};
        } else if (g2 == 3) {
            G[0][0] = {0.f,0.f}; G[0][1] = {0.f,-1.f}; G[1][0] = {0.f,1.f}; G[1][1] = {0.f,0.f};
        } else {
            G[0][0] = {1.f,0.f}; G[0][1] = {0.f,0.f}; G[1][0] = {0.f,0.f}; G[1][1] = {-1.f,0.f};
        }
        C2 R[2][2];
        for (int r = 0; r < 2; r++)
            for (int cc = 0; cc < 2; cc++)
                R[r][cc] = cxa(cxm(G[r][0], A[0][cc]), cxm(G[r][1], A[1][cc]));
        A[0][0] = R[0][0]; A[0][1] = R[0][1]; A[1][0] = R[1][0]; A[1][1] = R[1][1];
        haveA = true;
    }
    int atype = 0;
    if (haveA) {
        bool offd  = (A[0][1].re != 0.f) || (A[0][1].im != 0.f) ||
                     (A[1][0].re != 0.f) || (A[1][0].im != 0.f);
        bool anyim = (A[0][0].im != 0.f) || (A[0][1].im != 0.f) ||
                     (A[1][0].im != 0.f) || (A[1][1].im != 0.f);
        atype = offd ? (anyim ? 3 : 2) : 1;
    }
    int code = (dry[di] & 1) | (atype << 1) | ((g2 >= 5 ? g2 : 0) << 3);
    g_code[i] = code;
    g_mat[2 * i]     = make_float4(A[0][0].re, A[0][0].im, A[0][1].re, A[0][1].im);
    g_mat[2 * i + 1] = make_float4(A[1][0].re, A[1][0].im, A[1][1].re, A[1][1].im);
}

// ---------------------------------------------------------------------------

template<int NODE>
__device__ __forceinline__ void do_node(float re[8], float im[8], int lane,
                                        int layer, float fc_, float fs_) {
    constexpr int B  = 7 - NODE;
    constexpr int B1 = 7 - ((NODE + 1) & 7);
    constexpr int B2 = 7 - ((NODE + 2) & 7);

    const int idx = layer * 8 + NODE;
    int code = __ldg(&g_code[idx]);
    int atype = (code >> 1) & 3;

    if (code & 1) {   // RY present: fold into A at runtime (warp-uniform scalars)
        float c = __shfl_sync(FULLMASK, fc_, NODE);
        float s = __shfl_sync(FULLMASK, fs_, NODE);
        if (atype == 0) {
            ap_real<B>(re, im, lane, c, -s, s, c);               // pure RY
        } else if (atype == 2) {
            float4 r0 = __ldg(&g_mat[2 * idx]);
            float4 r1 = __ldg(&g_mat[2 * idx + 1]);
            // M = A * RY(theta), real
            float u00 = fmaf(r0.x, c,  r0.z * s);
            float u01 = fmaf(r0.z, c, -r0.x * s);
            float u10 = fmaf(r1.x, c,  r1.z * s);
            float u11 = fmaf(r1.z, c, -r1.x * s);
            ap_real<B>(re, im, lane, u00, u01, u10, u11);
        } else {       // atype 1 or 3: complex M = A * RY(theta)
            float4 r0 = __ldg(&g_mat[2 * idx]);
            float4 r1 = __ldg(&g_mat[2 * idx + 1]);
            float m00r = fmaf(r0.x, c,  r0.z * s), m00i = fmaf(r0.y, c,  r0.w * s);
            float m01r = fmaf(r0.z, c, -r0.x * s), m01i = fmaf(r0.w, c, -r0.y * s);
            float m10r = fmaf(r1.x, c,  r1.z * s), m10i = fmaf(r1.y, c,  r1.w * s);
            float m11r = fmaf(r1.z, c, -r1.x * s), m11i = fmaf(r1.w, c, -r1.y * s);
            ap_cplx<B>(re, im, lane, m00r, m00i, m01r, m01i, m10r, m10i, m11r, m11i);
        }
    } else if (atype) {
        float4 r0 = __ldg(&g_mat[2 * idx]);
        float4 r1 = __ldg(&g_mat[2 * idx + 1]);
        if (atype == 1) {
            ap_diag<B>(re, im, lane, r0.x, r0.y, r1.z, r1.w);
        } else if (atype == 2) {
            ap_real<B>(re, im, lane, r0.x, r0.z, r1.x, r1.z);
        } else {
            ap_cplx<B>(re, im, lane, r0.x, r0.y, r0.z, r0.w, r1.x, r1.y, r1.z, r1.w);
        }
    }

    int g2 = (code >> 3) & 15;
    if (g2) {
        switch (g2) {
            case 5: g_cx<B1, (1 << B)>(re, im, lane); break;              // CNOT
            case 6: g_cswap<B1, B2, B>(re, im, lane); break;              // CSWAP
            case 7: g_cx<B2, (1 << B) | (1 << B1)>(re, im, lane); break;  // Toffoli
            case 8: g_cz<B, B1>(re, im, lane); break;                     // CZ
            default: break;
        }
    }
}

__global__ void __launch_bounds__(256) qsim_kernel(
    const float* __restrict__ feats,   // [B, 8]
    float* __restrict__ out,           // [B, 8]
    int batch) {
    int w = (int)((blockIdx.x * blockDim.x + threadIdx.x) >> 5);
    int lane = threadIdx.x & 31;
    if (w >= batch) return;

    float fv = feats[w * 8 + (lane & 7)];
    float fs_, fc_;
    __sincosf(0.5f * fv, &fs_, &fc_);

    // H^8 |0...0>  ==  uniform 1/16 real amplitude
    float re[8], im[8];
#pragma unroll
    for (int r = 0; r < 8; r++) { re[r] = 0.0625f; im[r] = 0.0f; }

#pragma unroll 1
    for (int layer = 0; layer < 6; ++layer) {
        do_node<0>(re, im, lane, layer, fc_, fs_);
        do_node<1>(re, im, lane, layer, fc_, fs_);
        do_node<2>(re, im, lane, layer, fc_, fs_);
        do_node<3>(re, im, lane, layer, fc_, fs_);
        do_node<4>(re, im, lane, layer, fc_, fs_);
        do_node<5>(re, im, lane, layer, fc_, fs_);
        do_node<6>(re, im, lane, layer, fc_, fs_);
        do_node<7>(re, im, lane, layer, fc_, fs_);
    }

    // Measurement: <Z_p> = sum_i |a_i|^2 * (1 - 2*bit_{7-p}(i)),  i = (r<<5)|lane
    float acc[8];
#pragma unroll
    for (int p = 0; p < 8; p++) acc[p] = 0.f;
    float sgl[8];
#pragma unroll
    for (int p = 3; p < 8; p++)
        sgl[p] = ((lane >> (7 - p)) & 1) ? -1.f : 1.f;
#pragma unroll
    for (int r = 0; r < 8; r++) {
        float pr = fmaf(re[r], re[r], im[r] * im[r]);
        acc[0] += ((r >> 2) & 1) ? -pr : pr;
        acc[1] += ((r >> 1) & 1) ? -pr : pr;
        acc[2] += (r & 1)        ? -pr : pr;
#pragma unroll
        for (int p = 3; p < 8; p++) acc[p] += sgl[p] * pr;
    }
#pragma unroll
    for (int p = 0; p < 8; p++) {
#pragma unroll
        for (int off = 16; off; off >>= 1)
            acc[p] += __shfl_xor_sync(FULLMASK, acc[p], off);
    }
    if (lane == 0) {
        float4* o = reinterpret_cast<float4*>(out + (size_t)w * 8);
        o[0] = make_float4(acc[0], acc[1], acc[2], acc[3]);
        o[1] = make_float4(acc[4], acc[5], acc[6], acc[7]);
    }
}

extern "C" void kernel_launch(void* const* d_in, const int* in_sizes, int n_in,
                              void* d_out, int out_size) {
    const float* feats = (const float*)d_in[0];   // [B, 8] float32
    const float* qp    = (const float*)d_in[1];   // [48]  float32
    const int* dry     = (const int*)d_in[2];     // [6,4] int32
    const int* drot    = (const int*)d_in[3];     // [6,4] int32
    const int* dg2     = (const int*)d_in[4];     // [6,4] int32
    float* out         = (float*)d_out;           // [B, 8] float32

    int batch = in_sizes[0] / 8;
    setup_kernel<<<1, 64>>>(qp, dry, drot, dg2);
    int threads = 256;
    int total_threads = batch * 32;
    int blocks = (total_threads + threads - 1) / threads;
    qsim_kernel<<<blocks, threads>>>(feats, out, batch);
}

// round 7
// speedup vs baseline: 1.0421x; 1.0421x over previous
#include <cuda_runtime.h>

#define FULLMASK 0xffffffffu
typedef unsigned long long u64;

// ---------------------------------------------------------------------------
// State: amplitude index i (8 bits) = (r << 5) | lane. wire w <-> bit (7-w).
// Bits 0..4 lane, 5..7 register. a[8] packed complex: lo32=re, hi32=im.
// Fused 1q chain per node (RY(theta)*ROT*G2_1q) applied as one 2x2.
// Dispatch codes live in __constant__ (copied from setup output) -> provably
// warp-uniform branches, no BSSY divergence management, no LDG on the
// decision path. Matrices stored in apply-ready packed form (no MOV packing).
// ---------------------------------------------------------------------------

__device__ __forceinline__ u64 pack2(float lo, float hi) {
    u64 r; asm("mov.b64 %0, {%1, %2};" : "=l"(r) : "f"(lo), "f"(hi)); return r;
}
__device__ __forceinline__ void unpack2(u64 v, float& lo, float& hi) {
    asm("mov.b64 {%0, %1}, %2;" : "=f"(lo), "=f"(hi) : "l"(v));
}
__device__ __forceinline__ u64 dup2(float x) { return pack2(x, x); }
__device__ __forceinline__ u64 fma2(u64 a, u64 b, u64 c) {
    u64 d; asm("fma.rn.f32x2 %0, %1, %2, %3;" : "=l"(d) : "l"(a), "l"(b), "l"(c)); return d;
}
__device__ __forceinline__ u64 mul2(u64 a, u64 b) {
    u64 d; asm("mul.rn.f32x2 %0, %1, %2;" : "=l"(d) : "l"(a), "l"(b)); return d;
}
__device__ __forceinline__ u64 swap2(u64 v) {
    float lo, hi; unpack2(v, lo, hi); return pack2(hi, lo);
}
template<int ML>
__device__ __forceinline__ u64 shfl2(u64 v) {
    float lo, hi; unpack2(v, lo, hi);
    lo = __shfl_xor_sync(FULLMASK, lo, ML);
    hi = __shfl_xor_sync(FULLMASK, hi, ML);
    return pack2(lo, hi);
}

// ------------------------- fused 1q applies ---------------------------------

// Real 2x2 [u00,u01;u10,u11]
template<int B>
__device__ __forceinline__ void ap_real(u64 a[8], int lane,
                                        float u00, float u01, float u10, float u11) {
    if constexpr (B >= 5) {
        constexpr int M = 1 << (B - 5);
        u64 c00 = dup2(u00), c01 = dup2(u01), c10 = dup2(u10), c11 = dup2(u11);
#pragma unroll
        for (int r = 0; r < 8; r++) {
            if ((r & M) == 0) {
                int r1 = r | M;
                u64 v0 = a[r], v1 = a[r1];
                a[r]  = fma2(c01, v1, mul2(c00, v0));
                a[r1] = fma2(c11, v1, mul2(c10, v0));
            }
        }
    } else {
        int bit = (lane >> B) & 1;
        u64 u = dup2(bit ? u11 : u00);
        u64 v = dup2(bit ? u10 : u01);
#pragma unroll
        for (int r = 0; r < 8; r++) {
            u64 p = shfl2<(1 << B)>(a[r]);
            a[r] = fma2(v, p, mul2(u, a[r]));
        }
    }
}

// Complex 2x2 in CE form: per entry r2=(re,re), i2=(-im,im).
template<int B>
__device__ __forceinline__ void ap_cplx_ce(u64 a[8], int lane,
        u64 r00, u64 i00, u64 r01, u64 i01,
        u64 r10, u64 i10, u64 r11, u64 i11) {
    if constexpr (B >= 5) {
        constexpr int M = 1 << (B - 5);
#pragma unroll
        for (int r = 0; r < 8; r++) {
            if ((r & M) == 0) {
                int r1 = r | M;
                u64 v0 = a[r], v1 = a[r1];
                u64 s0 = swap2(v0), s1 = swap2(v1);
                a[r]  = fma2(i01, s1, fma2(r01, v1, fma2(i00, s0, mul2(r00, v0))));
                a[r1] = fma2(i11, s1, fma2(r11, v1, fma2(i10, s0, mul2(r10, v0))));
            }
        }
    } else {
        int bit = (lane >> B) & 1;
        u64 ur = bit ? r11 : r00, ui = bit ? i11 : i00;
        u64 vr = bit ? r10 : r01, vi = bit ? i10 : i01;
#pragma unroll
        for (int r = 0; r < 8; r++) {
            u64 p = shfl2<(1 << B)>(a[r]);
            u64 t = fma2(ui, swap2(a[r]), mul2(ur, a[r]));
            a[r] = fma2(vi, swap2(p), fma2(vr, p, t));
        }
    }
}

// Diagonal complex (CE form d0, d1) — zero shuffles.
template<int B>
__device__ __forceinline__ void ap_diag_ce(u64 a[8], int lane,
                                           u64 r0, u64 i0, u64 r1, u64 i1) {
    if constexpr (B >= 5) {
        constexpr int M = 1 << (B - 5);
#pragma unroll
        for (int r = 0; r < 8; r++) {
            u64 rr = (r & M) ? r1 : r0;
            u64 ii = (r & M) ? i1 : i0;
            a[r] = fma2(ii, swap2(a[r]), mul2(rr, a[r]));
        }
    } else {
        int bit = (lane >> B) & 1;
        u64 rr = bit ? r1 : r0, ii = bit ? i1 : i0;
#pragma unroll
        for (int r = 0; r < 8; r++)
            a[r] = fma2(ii, swap2(a[r]), mul2(rr, a[r]));
    }
}

// ------------------------- multi-qubit gates --------------------------------

template<int T, int CM>
__device__ __forceinline__ void g_cx(u64 a[8], int lane) {
    constexpr int CML = CM & 31;
    constexpr int CMR = (CM >> 5) & 7;
    bool lp = ((lane & CML) == CML);
    if constexpr (T < 5) {
#pragma unroll
        for (int r = 0; r < 8; r++) {
            if ((r & CMR) == CMR) {
                u64 p = shfl2<(1 << T)>(a[r]);
                if constexpr (CML == 0) a[r] = p;
                else a[r] = lp ? p : a[r];
            }
        }
    } else {
        constexpr int MT = 1 << (T - 5);
#pragma unroll
        for (int r = 0; r < 8; r++) {
            if (((r & CMR) == CMR) && !(r & MT)) {
                int r1 = r | MT;
                u64 v0 = a[r], v1 = a[r1];
                if constexpr (CML == 0) { a[r] = v1; a[r1] = v0; }
                else { a[r] = lp ? v1 : v0; a[r1] = lp ? v0 : v1; }
            }
        }
    }
}

template<int BA, int BB>
__device__ __forceinline__ void g_cz(u64 a[8], int lane) {
    bool lp = true;
    if constexpr (BA < 5) lp = lp && (((lane >> BA) & 1) != 0);
    if constexpr (BB < 5) lp = lp && (((lane >> BB) & 1) != 0);
    u64 sg = dup2(lp ? -1.f : 1.f);
#pragma unroll
    for (int r = 0; r < 8; r++) {
        bool rp = true;
        if (BA >= 5) rp = rp && (((r >> (BA - 5)) & 1) != 0);
        if (BB >= 5) rp = rp && (((r >> (BB - 5)) & 1) != 0);
        if (rp) a[r] = mul2(sg, a[r]);
    }
}

template<int A, int Bb, int C>
__device__ __forceinline__ constexpr bool cswap_possible(int r) {
    bool possible = true;
    if (C >= 5 && !((r >> (C - 5)) & 1)) possible = false;
    if (A >= 5 && Bb >= 5 &&
        (((r >> (A - 5)) & 1) == ((r >> (Bb - 5)) & 1))) possible = false;
    return possible;
}

// CSWAP: GATHER-THEN-UPDATE (alias-safe).
template<int A, int Bb, int C>
__device__ __forceinline__ void g_cswap(u64 a[8], int lane) {
    constexpr int M  = (1 << A) | (1 << Bb);
    constexpr int ML = M & 31;
    constexpr int MR = (M >> 5) & 7;
    u64 pa[8];
#pragma unroll
    for (int r = 0; r < 8; r++) {
        if (cswap_possible<A, Bb, C>(r)) {
            u64 v = a[r ^ MR];
            if constexpr (ML != 0) v = shfl2<ML>(v);
            pa[r] = v;
        }
    }
    bool lctl = true;
    if constexpr (C < 5) lctl = (((lane >> C) & 1) != 0);
#pragma unroll
    for (int r = 0; r < 8; r++) {
        if (cswap_possible<A, Bb, C>(r)) {
            int ba = (A  < 5) ? ((lane >> A)  & 1) : ((r >> (A  - 5)) & 1);
            int bb = (Bb < 5) ? ((lane >> Bb) & 1) : ((r >> (Bb - 5)) & 1);
            bool ctl = lctl;
            if (C >= 5) ctl = (((r >> (C - 5)) & 1) != 0);
            bool sw = ctl && (ba != bb);
            a[r] = sw ? pa[r] : a[r];
        }
    }
}

// ---------------------------------------------------------------------------
// Setup output buffers.
// code bits [0:3) = q1 class: 0 none, 1 diag, 2 real, 3 cplx,
//                   4 ry-only, 5 ry+diag, 6 ry+real, 7 ry+cplx.
// code bits [3:6) = multiq: 0 none, 1 CNOT, 2 CSWAP, 3 TOF, 4 CZ.
// g_ce[4i+e]: CE form of entry e (r2 bits, i2 bits).
// g_raw[2i+row]: packed (re,im) rows for runtime RY folding.
// g_realmat[i]: (A00r, A01r, A10r, A11r).
// ---------------------------------------------------------------------------
__device__ ulonglong2 g_ce[192];
__device__ ulonglong2 g_raw[96];
__device__ float4 g_realmat[48];
__device__ int g_code_dev[48];
__constant__ int c_code[48];

struct C2 { float re, im; };
__device__ __forceinline__ C2 cxm(C2 a, C2 b) {
    C2 o; o.re = a.re * b.re - a.im * b.im; o.im = a.re * b.im + a.im * b.re; return o;
}
__device__ __forceinline__ C2 cxa(C2 a, C2 b) { C2 o; o.re = a.re + b.re; o.im = a.im + b.im; return o; }

__global__ void setup_kernel(const float* __restrict__ qp,
                             const int* __restrict__ dry,
                             const int* __restrict__ drot,
                             const int* __restrict__ dg2) {
    int i = threadIdx.x;
    if (i >= 48) return;
    int layer = i >> 3, node = i & 7;
    int di = layer * 4 + (node & 3);
    float s, c;
    __sincosf(0.5f * qp[i], &s, &c);

    C2 A[2][2] = {{{1.f,0.f},{0.f,0.f}},{{0.f,0.f},{1.f,0.f}}};
    bool haveA = false;
    int rot = drot[di];
    if (rot == 0) {        // RX
        A[0][0] = {c,0.f}; A[0][1] = {0.f,-s}; A[1][0] = {0.f,-s}; A[1][1] = {c,0.f};
        haveA = true;
    } else if (rot == 1) { // RY
        A[0][0] = {c,0.f}; A[0][1] = {-s,0.f}; A[1][0] = {s,0.f};  A[1][1] = {c,0.f};
        haveA = true;
    } else if (rot == 2) { // RZ
        A[0][0] = {c,-s};  A[0][1] = {0.f,0.f}; A[1][0] = {0.f,0.f}; A[1][1] = {c,s};
        haveA = true;
    }
    int g2 = dg2[di];
    if (g2 >= 1 && g2 <= 4) {
        const float rh = 0.70710678118654752440f;
        C2 G[2][2];
        if (g2 == 1) {
            G[0][0] = {rh,0.f}; G[0][1] = {rh,0.f}; G[1][0] = {rh,0.f}; G[1][1] = {-rh,0.f};
        } else if (g2 == 2) {
            G[0][0] = {0.f,0.f}; G[0][1] = {1.f,0.f}; G[1][0] = {1.f,0.f}; G[1][1] = {0.f,0.f};
        } else if (g2 == 3) {
            G[0][0] = {0.f,0.f}; G[0][1] = {0.f,-1.f}; G[1][0] = {0.f,1.f}; G[1][1] = {0.f,0.f};
        } else {
            G[0][0] = {1.f,0.f}; G[0][1] = {0.f,0.f}; G[1][0] = {0.f,0.f}; G[1][1] = {-1.f,0.f};
        }
        C2 R[2][2];
        for (int r = 0; r < 2; r++)
            for (int cc = 0; cc < 2; cc++)
                R[r][cc] = cxa(cxm(G[r][0], A[0][cc]), cxm(G[r][1], A[1][cc]));
        A[0][0] = R[0][0]; A[0][1] = R[0][1]; A[1][0] = R[1][0]; A[1][1] = R[1][1];
        haveA = true;
    }
    int atype = 0;
    if (haveA) {
        bool offd  = (A[0][1].re != 0.f) || (A[0][1].im != 0.f) ||
                     (A[1][0].re != 0.f) || (A[1][0].im != 0.f);
        bool anyim = (A[0][0].im != 0.f) || (A[0][1].im != 0.f) ||
                     (A[1][0].im != 0.f) || (A[1][1].im != 0.f);
        atype = offd ? (anyim ? 3 : 2) : 1;
    }
    int q1 = (dry[di] & 1) ? (4 + atype) : atype;    // note 4+0 = pure RY
    int mq = (g2 >= 5) ? (g2 - 4) : 0;               // 5..8 -> 1..4
    g_code_dev[i] = q1 | (mq << 3);

    g_raw[2 * i]     = make_ulonglong2(pack2(A[0][0].re, A[0][0].im),
                                       pack2(A[0][1].re, A[0][1].im));
    g_raw[2 * i + 1] = make_ulonglong2(pack2(A[1][0].re, A[1][0].im),
                                       pack2(A[1][1].re, A[1][1].im));
    g_ce[4 * i + 0] = make_ulonglong2(dup2(A[0][0].re), pack2(-A[0][0].im, A[0][0].im));
    g_ce[4 * i + 1] = make_ulonglong2(dup2(A[0][1].re), pack2(-A[0][1].im, A[0][1].im));
    g_ce[4 * i + 2] = make_ulonglong2(dup2(A[1][0].re), pack2(-A[1][0].im, A[1][0].im));
    g_ce[4 * i + 3] = make_ulonglong2(dup2(A[1][1].re), pack2(-A[1][1].im, A[1][1].im));
    g_realmat[i] = make_float4(A[0][0].re, A[0][1].re, A[1][0].re, A[1][1].re);
}

// ---------------------------------------------------------------------------

template<int NODE>
__device__ __forceinline__ void do_node(u64 a[8], int lane, int layer,
                                        float fc_, float fs_) {
    constexpr int B  = 7 - NODE;
    constexpr int B1 = 7 - ((NODE + 1) & 7);
    constexpr int B2 = 7 - ((NODE + 2) & 7);
    const int idx = layer * 8 + NODE;

    int code = c_code[idx];           // constant load -> provably uniform
    int q1 = code & 7;
    if (q1) {
        switch (q1) {
            case 1: {  // diag, no shuffles
                ulonglong2 e0 = __ldg(&g_ce[4 * idx]);
                ulonglong2 e3 = __ldg(&g_ce[4 * idx + 3]);
                ap_diag_ce<B>(a, lane, e0.x, e0.y, e3.x, e3.y);
            } break;
            case 2: {  // real
                float4 m = __ldg(&g_realmat[idx]);
                ap_real<B>(a, lane, m.x, m.y, m.z, m.w);
            } break;
            case 3: {  // complex
                ulonglong2 e0 = __ldg(&g_ce[4 * idx + 0]);
                ulonglong2 e1 = __ldg(&g_ce[4 * idx + 1]);
                ulonglong2 e2 = __ldg(&g_ce[4 * idx + 2]);
                ulonglong2 e3 = __ldg(&g_ce[4 * idx + 3]);
                ap_cplx_ce<B>(a, lane, e0.x, e0.y, e1.x, e1.y,
                                       e2.x, e2.y, e3.x, e3.y);
            } break;
            case 4: {  // pure RY
                float c = __shfl_sync(FULLMASK, fc_, NODE);
                float s = __shfl_sync(FULLMASK, fs_, NODE);
                ap_real<B>(a, lane, c, -s, s, c);
            } break;
            case 6: {  // RY folded into real A
                float c = __shfl_sync(FULLMASK, fc_, NODE);
                float s = __shfl_sync(FULLMASK, fs_, NODE);
                float4 m = __ldg(&g_realmat[idx]);
                float u00 = fmaf(m.x, c,  m.y * s);
                float u01 = fmaf(m.y, c, -m.x * s);
                float u10 = fmaf(m.z, c,  m.w * s);
                float u11 = fmaf(m.w, c, -m.z * s);
                ap_real<B>(a, lane, u00, u01, u10, u11);
            } break;
            default: {  // 5 or 7: RY folded into complex A
                float c = __shfl_sync(FULLMASK, fc_, NODE);
                float s = __shfl_sync(FULLMASK, fs_, NODE);
                ulonglong2 ra = __ldg(&g_raw[2 * idx]);
                ulonglong2 rb = __ldg(&g_raw[2 * idx + 1]);
                u64 c2 = dup2(c), s2 = dup2(s), ns2 = dup2(-s);
                u64 M00 = fma2(s2, ra.y, mul2(c2,  ra.x));
                u64 M01 = fma2(c2, ra.y, mul2(ns2, ra.x));
                u64 M10 = fma2(s2, rb.y, mul2(c2,  rb.x));
                u64 M11 = fma2(c2, rb.y, mul2(ns2, rb.x));
                float mr, mi;
                unpack2(M00, mr, mi); u64 r00 = dup2(mr), i00 = pack2(-mi, mi);
                unpack2(M01, mr, mi); u64 r01 = dup2(mr), i01 = pack2(-mi, mi);
                unpack2(M10, mr, mi); u64 r10 = dup2(mr), i10 = pack2(-mi, mi);
                unpack2(M11, mr, mi); u64 r11 = dup2(mr), i11 = pack2(-mi, mi);
                ap_cplx_ce<B>(a, lane, r00, i00, r01, i01, r10, i10, r11, i11);
            } break;
        }
    }
    int mq = (code >> 3) & 7;
    if (mq) {
        switch (mq) {
            case 1: g_cx<B1, (1 << B)>(a, lane); break;               // CNOT
            case 2: g_cswap<B1, B2, B>(a, lane); break;               // CSWAP
            case 3: g_cx<B2, (1 << B) | (1 << B1)>(a, lane); break;   // Toffoli
            default: g_cz<B, B1>(a, lane); break;                     // CZ
        }
    }
}

__global__ void __launch_bounds__(256) qsim_kernel(
    const float* __restrict__ feats,   // [B, 8]
    float* __restrict__ out,           // [B, 8]
    int batch) {
    int w = (int)((blockIdx.x * blockDim.x + threadIdx.x) >> 5);
    int lane = threadIdx.x & 31;
    if (w >= batch) return;

    float fv = feats[w * 8 + (lane & 7)];
    float fs_, fc_;
    __sincosf(0.5f * fv, &fs_, &fc_);

    // H^8 |0...0>  ==  uniform 1/16 real amplitude
    u64 a[8];
    u64 init = pack2(0.0625f, 0.0f);
#pragma unroll
    for (int r = 0; r < 8; r++) a[r] = init;

#pragma unroll 1
    for (int layer = 0; layer < 6; ++layer) {
        do_node<0>(a, lane, layer, fc_, fs_);
        do_node<1>(a, lane, layer, fc_, fs_);
        do_node<2>(a, lane, layer, fc_, fs_);
        do_node<3>(a, lane, layer, fc_, fs_);
        do_node<4>(a, lane, layer, fc_, fs_);
        do_node<5>(a, lane, layer, fc_, fs_);
        do_node<6>(a, lane, layer, fc_, fs_);
        do_node<7>(a, lane, layer, fc_, fs_);
    }

    // Measurement: <Z_p> = sum_i |a_i|^2 * (1 - 2*bit_{7-p}(i)),  i = (r<<5)|lane
    float acc[8];
#pragma unroll
    for (int p = 0; p < 8; p++) acc[p] = 0.f;
    float sgl[8];
#pragma unroll
    for (int p = 3; p < 8; p++)
        sgl[p] = ((lane >> (7 - p)) & 1) ? -1.f : 1.f;
#pragma unroll
    for (int r = 0; r < 8; r++) {
        float re, im;
        unpack2(a[r], re, im);
        float pr = fmaf(re, re, im * im);
        acc[0] += ((r >> 2) & 1) ? -pr : pr;
        acc[1] += ((r >> 1) & 1) ? -pr : pr;
        acc[2] += (r & 1)        ? -pr : pr;
#pragma unroll
        for (int p = 3; p < 8; p++) acc[p] += sgl[p] * pr;
    }
#pragma unroll
    for (int p = 0; p < 8; p++) {
#pragma unroll
        for (int off = 16; off; off >>= 1)
            acc[p] += __shfl_xor_sync(FULLMASK, acc[p], off);
    }
    if (lane == 0) {
        float4* o = reinterpret_cast<float4*>(out + (size_t)w * 8);
        o[0] = make_float4(acc[0], acc[1], acc[2], acc[3]);
        o[1] = make_float4(acc[4], acc[5], acc[6], acc[7]);
    }
}

extern "C" void kernel_launch(void* const* d_in, const int* in_sizes, int n_in,
                              void* d_out, int out_size) {
    const float* feats = (const float*)d_in[0];   // [B, 8] float32
    const float* qp    = (const float*)d_in[1];   // [48]  float32
    const int* dry     = (const int*)d_in[2];     // [6,4] int32
    const int* drot    = (const int*)d_in[3];     // [6,4] int32
    const int* dg2     = (const int*)d_in[4];     // [6,4] int32
    float* out         = (float*)d_out;           // [B, 8] float32

    int batch = in_sizes[0] / 8;

    setup_kernel<<<1, 64>>>(qp, dry, drot, dg2);

    // Copy dispatch codes into __constant__ (D2D async memcpy node; capturable).
    void* code_src = nullptr;
    cudaGetSymbolAddress(&code_src, g_code_dev);
    cudaMemcpyToSymbolAsync(c_code, code_src, 48 * sizeof(int), 0,
                            cudaMemcpyDeviceToDevice);

    int threads = 256;
    int total_threads = batch * 32;
    int blocks = (total_threads + threads - 1) / threads;
    qsim_kernel<<<blocks, threads>>>(feats, out, batch);
}

// round 8
// speedup vs baseline: 1.2032x; 1.1546x over previous
#include <cuda_runtime.h>

#define FULLMASK 0xffffffffu
typedef unsigned long long u64;

// ---------------------------------------------------------------------------
// TWO SAMPLES PER WARP.
// Amplitude index i (8 bits) = (r << 4) | (lane & 15). Sample = 2*warp + lane>>4.
// wire w <-> bit (7-w). Bits 0..3 = lane bits 0..3, bits 4..7 = register bits.
// Lane bit 4 selects the sample; XOR shuffle masks < 16 never cross it.
// Each lane holds a[16] packed complex amplitudes (lo32=re, hi32=im).
// Per-node fused 1q matrix (setup-precomputed uniform part, per-sample RY
// folded at runtime) -> per-node overhead amortized over 2 samples, and only
// 4/8 wires need lane exchanges (was 5/8).
// ---------------------------------------------------------------------------

constexpr int LB = 4;   // number of lane bits

__device__ __forceinline__ u64 pack2(float lo, float hi) {
    u64 r; asm("mov.b64 %0, {%1, %2};" : "=l"(r) : "f"(lo), "f"(hi)); return r;
}
__device__ __forceinline__ void unpack2(u64 v, float& lo, float& hi) {
    asm("mov.b64 {%0, %1}, %2;" : "=f"(lo), "=f"(hi) : "l"(v));
}
__device__ __forceinline__ u64 dup2(float x) { return pack2(x, x); }
__device__ __forceinline__ u64 fma2(u64 a, u64 b, u64 c) {
    u64 d; asm("fma.rn.f32x2 %0, %1, %2, %3;" : "=l"(d) : "l"(a), "l"(b), "l"(c)); return d;
}
__device__ __forceinline__ u64 mul2(u64 a, u64 b) {
    u64 d; asm("mul.rn.f32x2 %0, %1, %2;" : "=l"(d) : "l"(a), "l"(b)); return d;
}
__device__ __forceinline__ u64 swap2(u64 v) {
    float lo, hi; unpack2(v, lo, hi); return pack2(hi, lo);
}
template<int ML>
__device__ __forceinline__ u64 shfl2(u64 v) {
    float lo, hi; unpack2(v, lo, hi);
    lo = __shfl_xor_sync(FULLMASK, lo, ML);
    hi = __shfl_xor_sync(FULLMASK, hi, ML);
    return pack2(lo, hi);
}

// ------------------------- fused 1q applies ---------------------------------

// Real 2x2 [u00,u01;u10,u11]; coefficients may differ per half-warp (2 samples).
template<int B>
__device__ __forceinline__ void ap_real(u64 a[16], int lane,
                                        float u00, float u01, float u10, float u11) {
    if constexpr (B >= LB) {
        constexpr int M = 1 << (B - LB);
        u64 c00 = dup2(u00), c01 = dup2(u01), c10 = dup2(u10), c11 = dup2(u11);
#pragma unroll
        for (int r = 0; r < 16; r++) {
            if ((r & M) == 0) {
                int r1 = r | M;
                u64 v0 = a[r], v1 = a[r1];
                a[r]  = fma2(c01, v1, mul2(c00, v0));
                a[r1] = fma2(c11, v1, mul2(c10, v0));
            }
        }
    } else {
        int bit = (lane >> B) & 1;
        u64 u = dup2(bit ? u11 : u00);
        u64 v = dup2(bit ? u10 : u01);
#pragma unroll
        for (int r = 0; r < 16; r++) {
            u64 p = shfl2<(1 << B)>(a[r]);
            a[r] = fma2(v, p, mul2(u, a[r]));
        }
    }
}

// Complex 2x2 in CE form: per entry r2=(re,re), i2=(-im,im).
template<int B>
__device__ __forceinline__ void ap_cplx_ce(u64 a[16], int lane,
        u64 r00, u64 i00, u64 r01, u64 i01,
        u64 r10, u64 i10, u64 r11, u64 i11) {
    if constexpr (B >= LB) {
        constexpr int M = 1 << (B - LB);
#pragma unroll
        for (int r = 0; r < 16; r++) {
            if ((r & M) == 0) {
                int r1 = r | M;
                u64 v0 = a[r], v1 = a[r1];
                u64 s0 = swap2(v0), s1 = swap2(v1);
                a[r]  = fma2(i01, s1, fma2(r01, v1, fma2(i00, s0, mul2(r00, v0))));
                a[r1] = fma2(i11, s1, fma2(r11, v1, fma2(i10, s0, mul2(r10, v0))));
            }
        }
    } else {
        int bit = (lane >> B) & 1;
        u64 ur = bit ? r11 : r00, ui = bit ? i11 : i00;
        u64 vr = bit ? r10 : r01, vi = bit ? i10 : i01;
#pragma unroll
        for (int r = 0; r < 16; r++) {
            u64 p = shfl2<(1 << B)>(a[r]);
            u64 t = fma2(ui, swap2(a[r]), mul2(ur, a[r]));
            a[r] = fma2(vi, swap2(p), fma2(vr, p, t));
        }
    }
}

// Diagonal complex (CE form d0, d1) — zero shuffles.
template<int B>
__device__ __forceinline__ void ap_diag_ce(u64 a[16], int lane,
                                           u64 r0, u64 i0, u64 r1, u64 i1) {
    if constexpr (B >= LB) {
        constexpr int M = 1 << (B - LB);
#pragma unroll
        for (int r = 0; r < 16; r++) {
            u64 rr = (r & M) ? r1 : r0;
            u64 ii = (r & M) ? i1 : i0;
            a[r] = fma2(ii, swap2(a[r]), mul2(rr, a[r]));
        }
    } else {
        int bit = (lane >> B) & 1;
        u64 rr = bit ? r1 : r0, ii = bit ? i1 : i0;
#pragma unroll
        for (int r = 0; r < 16; r++)
            a[r] = fma2(ii, swap2(a[r]), mul2(rr, a[r]));
    }
}

// ------------------------- multi-qubit gates --------------------------------

// Controlled-X: flip bit T where all CM bits set. CM==0 -> plain X.
template<int T, int CM>
__device__ __forceinline__ void g_cx(u64 a[16], int lane) {
    constexpr int CML = CM & (( 1 << LB) - 1);
    constexpr int CMR = (CM >> LB) & 15;
    bool lp = ((lane & CML) == CML);
    if constexpr (T < LB) {
#pragma unroll
        for (int r = 0; r < 16; r++) {
            if ((r & CMR) == CMR) {
                u64 p = shfl2<(1 << T)>(a[r]);
                if constexpr (CML == 0) a[r] = p;
                else a[r] = lp ? p : a[r];
            }
        }
    } else {
        constexpr int MT = 1 << (T - LB);
#pragma unroll
        for (int r = 0; r < 16; r++) {
            if (((r & CMR) == CMR) && !(r & MT)) {
                int r1 = r | MT;
                u64 v0 = a[r], v1 = a[r1];
                if constexpr (CML == 0) { a[r] = v1; a[r1] = v0; }
                else { a[r] = lp ? v1 : v0; a[r1] = lp ? v0 : v1; }
            }
        }
    }
}

// CZ on bits BA, BB
template<int BA, int BB>
__device__ __forceinline__ void g_cz(u64 a[16], int lane) {
    bool lp = true;
    if constexpr (BA < LB) lp = lp && (((lane >> BA) & 1) != 0);
    if constexpr (BB < LB) lp = lp && (((lane >> BB) & 1) != 0);
    u64 sg = dup2(lp ? -1.f : 1.f);
#pragma unroll
    for (int r = 0; r < 16; r++) {
        bool rp = true;
        if (BA >= LB) rp = rp && (((r >> (BA - LB)) & 1) != 0);
        if (BB >= LB) rp = rp && (((r >> (BB - LB)) & 1) != 0);
        if (rp) a[r] = mul2(sg, a[r]);
    }
}

template<int A, int Bb, int C>
__device__ __forceinline__ constexpr bool cswap_possible(int r) {
    bool possible = true;
    if (C >= LB && !((r >> (C - LB)) & 1)) possible = false;
    if (A >= LB && Bb >= LB &&
        (((r >> (A - LB)) & 1) == ((r >> (Bb - LB)) & 1))) possible = false;
    return possible;
}

// CSWAP: control C; swap bits A,Bb where they differ. GATHER-THEN-UPDATE.
template<int A, int Bb, int C>
__device__ __forceinline__ void g_cswap(u64 a[16], int lane) {
    constexpr int M  = (1 << A) | (1 << Bb);
    constexpr int ML = M & ((1 << LB) - 1);
    constexpr int MR = (M >> LB) & 15;
    u64 pa[16];
#pragma unroll
    for (int r = 0; r < 16; r++) {
        if (cswap_possible<A, Bb, C>(r)) {
            u64 v = a[r ^ MR];
            if constexpr (ML != 0) v = shfl2<ML>(v);
            pa[r] = v;
        }
    }
    bool lctl = true;
    if constexpr (C < LB) lctl = (((lane >> C) & 1) != 0);
#pragma unroll
    for (int r = 0; r < 16; r++) {
        if (cswap_possible<A, Bb, C>(r)) {
            int ba = (A  < LB) ? ((lane >> A)  & 1) : ((r >> (A  - LB)) & 1);
            int bb = (Bb < LB) ? ((lane >> Bb) & 1) : ((r >> (Bb - LB)) & 1);
            bool ctl = lctl;
            if (C >= LB) ctl = (((r >> (C - LB)) & 1) != 0);
            bool sw = ctl && (ba != bb);
            a[r] = sw ? pa[r] : a[r];
        }
    }
}

// ---------------------------------------------------------------------------
// Setup (same as R7): per (layer,node) A = G2_1q * ROT, classified.
// code bits [0:3) = q1: 0 none,1 diag,2 real,3 cplx,4 ry,5 ry+diag,6 ry+real,7 ry+cplx
// code bits [3:6) = multiq: 0 none, 1 CNOT, 2 CSWAP, 3 TOF, 4 CZ.
// ---------------------------------------------------------------------------
__device__ ulonglong2 g_ce[192];
__device__ ulonglong2 g_raw[96];
__device__ float4 g_realmat[48];
__device__ int g_code_dev[48];
__constant__ int c_code[48];

struct C2 { float re, im; };
__device__ __forceinline__ C2 cxm(C2 a, C2 b) {
    C2 o; o.re = a.re * b.re - a.im * b.im; o.im = a.re * b.im + a.im * b.re; return o;
}
__device__ __forceinline__ C2 cxa(C2 a, C2 b) { C2 o; o.re = a.re + b.re; o.im = a.im + b.im; return o; }

__global__ void setup_kernel(const float* __restrict__ qp,
                             const int* __restrict__ dry,
                             const int* __restrict__ drot,
                             const int* __restrict__ dg2) {
    int i = threadIdx.x;
    if (i >= 48) return;
    int layer = i >> 3, node = i & 7;
    int di = layer * 4 + (node & 3);
    float s, c;
    __sincosf(0.5f * qp[i], &s, &c);

    C2 A[2][2] = {{{1.f,0.f},{0.f,0.f}},{{0.f,0.f},{1.f,0.f}}};
    bool haveA = false;
    int rot = drot[di];
    if (rot == 0) {
        A[0][0] = {c,0.f}; A[0][1] = {0.f,-s}; A[1][0] = {0.f,-s}; A[1][1] = {c,0.f};
        haveA = true;
    } else if (rot == 1) {
        A[0][0] = {c,0.f}; A[0][1] = {-s,0.f}; A[1][0] = {s,0.f};  A[1][1] = {c,0.f};
        haveA = true;
    } else if (rot == 2) {
        A[0][0] = {c,-s};  A[0][1] = {0.f,0.f}; A[1][0] = {0.f,0.f}; A[1][1] = {c,s};
        haveA = true;
    }
    int g2 = dg2[di];
    if (g2 >= 1 && g2 <= 4) {
        const float rh = 0.70710678118654752440f;
        C2 G[2][2];
        if (g2 == 1) {
            G[0][0] = {rh,0.f}; G[0][1] = {rh,0.f}; G[1][0] = {rh,0.f}; G[1][1] = {-rh,0.f};
        } else if (g2 == 2) {
            G[0][0] = {0.f,0.f}; G[0][1] = {1.f,0.f}; G[1][0] = {1.f,0.f}; G[1][1] = {0.f,0.f};
        } else if (g2 == 3) {
            G[0][0] = {0.f,0.f}; G[0][1] = {0.f,-1.f}; G[1][0] = {0.f,1.f}; G[1][1] = {0.f,0.f};
        } else {
            G[0][0] = {1.f,0.f}; G[0][1] = {0.f,0.f}; G[1][0] = {0.f,0.f}; G[1][1] = {-1.f,0.f};
        }
        C2 R[2][2];
        for (int r = 0; r < 2; r++)
            for (int cc = 0; cc < 2; cc++)
                R[r][cc] = cxa(cxm(G[r][0], A[0][cc]), cxm(G[r][1], A[1][cc]));
        A[0][0] = R[0][0]; A[0][1] = R[0][1]; A[1][0] = R[1][0]; A[1][1] = R[1][1];
        haveA = true;
    }
    int atype = 0;
    if (haveA) {
        bool offd  = (A[0][1].re != 0.f) || (A[0][1].im != 0.f) ||
                     (A[1][0].re != 0.f) || (A[1][0].im != 0.f);
        bool anyim = (A[0][0].im != 0.f) || (A[0][1].im != 0.f) ||
                     (A[1][0].im != 0.f) || (A[1][1].im != 0.f);
        atype = offd ? (anyim ? 3 : 2) : 1;
    }
    int q1 = (dry[di] & 1) ? (4 + atype) : atype;
    int mq = (g2 >= 5) ? (g2 - 4) : 0;
    g_code_dev[i] = q1 | (mq << 3);

    g_raw[2 * i]     = make_ulonglong2(pack2(A[0][0].re, A[0][0].im),
                                       pack2(A[0][1].re, A[0][1].im));
    g_raw[2 * i + 1] = make_ulonglong2(pack2(A[1][0].re, A[1][0].im),
                                       pack2(A[1][1].re, A[1][1].im));
    g_ce[4 * i + 0] = make_ulonglong2(dup2(A[0][0].re), pack2(-A[0][0].im, A[0][0].im));
    g_ce[4 * i + 1] = make_ulonglong2(dup2(A[0][1].re), pack2(-A[0][1].im, A[0][1].im));
    g_ce[4 * i + 2] = make_ulonglong2(dup2(A[1][0].re), pack2(-A[1][0].im, A[1][0].im));
    g_ce[4 * i + 3] = make_ulonglong2(dup2(A[1][1].re), pack2(-A[1][1].im, A[1][1].im));
    g_realmat[i] = make_float4(A[0][0].re, A[0][1].re, A[1][0].re, A[1][1].re);
}

// ---------------------------------------------------------------------------

template<int NODE>
__device__ __forceinline__ void do_node(u64 a[16], int lane, int layer,
                                        float fc_, float fs_) {
    constexpr int B  = 7 - NODE;
    constexpr int B1 = 7 - ((NODE + 1) & 7);
    constexpr int B2 = 7 - ((NODE + 2) & 7);
    const int idx = layer * 8 + NODE;

    int code = c_code[idx];           // constant -> provably uniform
    int q1 = code & 7;
    if (q1) {
        switch (q1) {
            case 1: {
                ulonglong2 e0 = __ldg(&g_ce[4 * idx]);
                ulonglong2 e3 = __ldg(&g_ce[4 * idx + 3]);
                ap_diag_ce<B>(a, lane, e0.x, e0.y, e3.x, e3.y);
            } break;
            case 2: {
                float4 m = __ldg(&g_realmat[idx]);
                ap_real<B>(a, lane, m.x, m.y, m.z, m.w);
            } break;
            case 3: {
                ulonglong2 e0 = __ldg(&g_ce[4 * idx + 0]);
                ulonglong2 e1 = __ldg(&g_ce[4 * idx + 1]);
                ulonglong2 e2 = __ldg(&g_ce[4 * idx + 2]);
                ulonglong2 e3 = __ldg(&g_ce[4 * idx + 3]);
                ap_cplx_ce<B>(a, lane, e0.x, e0.y, e1.x, e1.y,
                                       e2.x, e2.y, e3.x, e3.y);
            } break;
            case 4: {  // pure RY — width-16 broadcast picks this half-warp's sample
                float c = __shfl_sync(FULLMASK, fc_, NODE, 16);
                float s = __shfl_sync(FULLMASK, fs_, NODE, 16);
                ap_real<B>(a, lane, c, -s, s, c);
            } break;
            case 6: {  // RY folded into real A (per-half-warp values; same instr count)
                float c = __shfl_sync(FULLMASK, fc_, NODE, 16);
                float s = __shfl_sync(FULLMASK, fs_, NODE, 16);
                float4 m = __ldg(&g_realmat[idx]);
                float u00 = fmaf(m.x, c,  m.y * s);
                float u01 = fmaf(m.y, c, -m.x * s);
                float u10 = fmaf(m.z, c,  m.w * s);
                float u11 = fmaf(m.w, c, -m.z * s);
                ap_real<B>(a, lane, u00, u01, u10, u11);
            } break;
            default: {  // 5 or 7: RY folded into complex A
                float c = __shfl_sync(FULLMASK, fc_, NODE, 16);
                float s = __shfl_sync(FULLMASK, fs_, NODE, 16);
                ulonglong2 ra = __ldg(&g_raw[2 * idx]);
                ulonglong2 rb = __ldg(&g_raw[2 * idx + 1]);
                u64 c2 = dup2(c), s2 = dup2(s), ns2 = dup2(-s);
                u64 M00 = fma2(s2, ra.y, mul2(c2,  ra.x));
                u64 M01 = fma2(c2, ra.y, mul2(ns2, ra.x));
                u64 M10 = fma2(s2, rb.y, mul2(c2,  rb.x));
                u64 M11 = fma2(c2, rb.y, mul2(ns2, rb.x));
                float mr, mi;
                unpack2(M00, mr, mi); u64 r00 = dup2(mr), i00 = pack2(-mi, mi);
                unpack2(M01, mr, mi); u64 r01 = dup2(mr), i01 = pack2(-mi, mi);
                unpack2(M10, mr, mi); u64 r10 = dup2(mr), i10 = pack2(-mi, mi);
                unpack2(M11, mr, mi); u64 r11 = dup2(mr), i11 = pack2(-mi, mi);
                ap_cplx_ce<B>(a, lane, r00, i00, r01, i01, r10, i10, r11, i11);
            } break;
        }
    }
    int mq = (code >> 3) & 7;
    if (mq) {
        switch (mq) {
            case 1: g_cx<B1, (1 << B)>(a, lane); break;               // CNOT
            case 2: g_cswap<B1, B2, B>(a, lane); break;               // CSWAP
            case 3: g_cx<B2, (1 << B) | (1 << B1)>(a, lane); break;   // Toffoli
            default: g_cz<B, B1>(a, lane); break;                     // CZ
        }
    }
}

__global__ void __launch_bounds__(256) qsim_kernel(
    const float* __restrict__ feats,   // [B, 8]
    float* __restrict__ out,           // [B, 8]
    int nwarps) {
    int w = (int)((blockIdx.x * blockDim.x + threadIdx.x) >> 5);
    int lane = threadIdx.x & 31;
    if (w >= nwarps) return;

    int sample = 2 * w + (lane >> 4);       // half-warp's sample
    float fv = feats[sample * 8 + (lane & 7)];
    float fs_, fc_;
    __sincosf(0.5f * fv, &fs_, &fc_);

    // H^8 |0...0>  ==  uniform 1/16 real amplitude
    u64 a[16];
    u64 init = pack2(0.0625f, 0.0f);
#pragma unroll
    for (int r = 0; r < 16; r++) a[r] = init;

#pragma unroll 1
    for (int layer = 0; layer < 6; ++layer) {
        do_node<0>(a, lane, layer, fc_, fs_);
        do_node<1>(a, lane, layer, fc_, fs_);
        do_node<2>(a, lane, layer, fc_, fs_);
        do_node<3>(a, lane, layer, fc_, fs_);
        do_node<4>(a, lane, layer, fc_, fs_);
        do_node<5>(a, lane, layer, fc_, fs_);
        do_node<6>(a, lane, layer, fc_, fs_);
        do_node<7>(a, lane, layer, fc_, fs_);
    }

    // <Z_p> = sum_i |a_i|^2 * (1 - 2*bit_{7-p}(i)),  i = (r<<4) | (lane&15)
    float acc[8];
#pragma unroll
    for (int p = 0; p < 8; p++) acc[p] = 0.f;
    float sgl[8];
#pragma unroll
    for (int p = 4; p < 8; p++)
        sgl[p] = ((lane >> (7 - p)) & 1) ? -1.f : 1.f;   // lane bits 3..0
#pragma unroll
    for (int r = 0; r < 16; r++) {
        float re, im;
        unpack2(a[r], re, im);
        float pr = fmaf(re, re, im * im);
        // p=0..3 -> bits 7..4 -> r bits 3..0: compile-time signs
        acc[0] += ((r >> 3) & 1) ? -pr : pr;
        acc[1] += ((r >> 2) & 1) ? -pr : pr;
        acc[2] += ((r >> 1) & 1) ? -pr : pr;
        acc[3] += (r & 1)        ? -pr : pr;
#pragma unroll
        for (int p = 4; p < 8; p++) acc[p] += sgl[p] * pr;
    }
#pragma unroll
    for (int p = 0; p < 8; p++) {
#pragma unroll
        for (int off = 8; off; off >>= 1)   // width-16 butterfly (stays in half)
            acc[p] += __shfl_xor_sync(FULLMASK, acc[p], off);
    }
    if ((lane & 15) == 0) {
        float4* o = reinterpret_cast<float4*>(out + (size_t)sample * 8);
        o[0] = make_float4(acc[0], acc[1], acc[2], acc[3]);
        o[1] = make_float4(acc[4], acc[5], acc[6], acc[7]);
    }
}

extern "C" void kernel_launch(void* const* d_in, const int* in_sizes, int n_in,
                              void* d_out, int out_size) {
    const float* feats = (const float*)d_in[0];   // [B, 8] float32
    const float* qp    = (const float*)d_in[1];   // [48]  float32
    const int* dry     = (const int*)d_in[2];     // [6,4] int32
    const int* drot    = (const int*)d_in[3];     // [6,4] int32
    const int* dg2     = (const int*)d_in[4];     // [6,4] int32
    float* out         = (float*)d_out;           // [B, 8] float32

    int batch = in_sizes[0] / 8;
    int nwarps = batch / 2;                       // 2 samples per warp

    setup_kernel<<<1, 64>>>(qp, dry, drot, dg2);

    void* code_src = nullptr;
    cudaGetSymbolAddress(&code_src, g_code_dev);
    cudaMemcpyToSymbolAsync(c_code, code_src, 48 * sizeof(int), 0,
                            cudaMemcpyDeviceToDevice);

    int threads = 256;
    long long total_threads = (long long)nwarps * 32;
    int blocks = (int)((total_threads + threads - 1) / threads);
    qsim_kernel<<<blocks, threads>>>(feats, out, nwarps);
}

// round 10
// speedup vs baseline: 1.2066x; 1.0028x over previous
#include <cuda_runtime.h>

#define FULLMASK 0xffffffffu
typedef unsigned long long u64;

// ---------------------------------------------------------------------------
// TWO SAMPLES PER WARP.
// Amplitude index i (8 bits) = (r << 4) | (lane & 15). Sample = 2*warp + lane>>4.
// wire w <-> bit (7-w). Bits 0..3 = lane bits, 4..7 = register bits.
// Lane bit 4 selects the sample; XOR shuffle masks < 16 never cross it.
// a[16] packed complex amplitudes (lo32=re, hi32=im).
// R10: CSWAP split into 3 static shapes (fixes R9's wrong pairing when both
// swap bits are register bits: pairs are 01<->10, not 00<->11).
// ---------------------------------------------------------------------------

constexpr int LB = 4;   // number of lane bits

__device__ __forceinline__ u64 pack2(float lo, float hi) {
    u64 r; asm("mov.b64 %0, {%1, %2};" : "=l"(r) : "f"(lo), "f"(hi)); return r;
}
__device__ __forceinline__ void unpack2(u64 v, float& lo, float& hi) {
    asm("mov.b64 {%0, %1}, %2;" : "=f"(lo), "=f"(hi) : "l"(v));
}
__device__ __forceinline__ u64 dup2(float x) { return pack2(x, x); }
__device__ __forceinline__ u64 fma2(u64 a, u64 b, u64 c) {
    u64 d; asm("fma.rn.f32x2 %0, %1, %2, %3;" : "=l"(d) : "l"(a), "l"(b), "l"(c)); return d;
}
__device__ __forceinline__ u64 mul2(u64 a, u64 b) {
    u64 d; asm("mul.rn.f32x2 %0, %1, %2;" : "=l"(d) : "l"(a), "l"(b)); return d;
}
__device__ __forceinline__ u64 swap2(u64 v) {
    float lo, hi; unpack2(v, lo, hi); return pack2(hi, lo);
}
template<int ML>
__device__ __forceinline__ u64 shfl2(u64 v) {
    float lo, hi; unpack2(v, lo, hi);
    lo = __shfl_xor_sync(FULLMASK, lo, ML);
    hi = __shfl_xor_sync(FULLMASK, hi, ML);
    return pack2(lo, hi);
}

// ------------------------- fused 1q applies ---------------------------------

// Real 2x2 [u00,u01;u10,u11]; coefficients may differ per half-warp.
template<int B>
__device__ __forceinline__ void ap_real(u64 a[16], int lane,
                                        float u00, float u01, float u10, float u11) {
    if constexpr (B >= LB) {
        constexpr int M = 1 << (B - LB);
        u64 c00 = dup2(u00), c01 = dup2(u01), c10 = dup2(u10), c11 = dup2(u11);
#pragma unroll
        for (int r = 0; r < 16; r++) {
            if ((r & M) == 0) {
                int r1 = r | M;
                u64 v0 = a[r], v1 = a[r1];
                a[r]  = fma2(c01, v1, mul2(c00, v0));
                a[r1] = fma2(c11, v1, mul2(c10, v0));
            }
        }
    } else {
        int bit = (lane >> B) & 1;
        u64 u = dup2(bit ? u11 : u00);
        u64 v = dup2(bit ? u10 : u01);
#pragma unroll
        for (int r = 0; r < 16; r++) {
            u64 p = shfl2<(1 << B)>(a[r]);
            a[r] = fma2(v, p, mul2(u, a[r]));
        }
    }
}

// Complex 2x2 in CE form: per entry r2=(re,re), i2=(-im,im).
template<int B>
__device__ __forceinline__ void ap_cplx_ce(u64 a[16], int lane,
        u64 r00, u64 i00, u64 r01, u64 i01,
        u64 r10, u64 i10, u64 r11, u64 i11) {
    if constexpr (B >= LB) {
        constexpr int M = 1 << (B - LB);
#pragma unroll
        for (int r = 0; r < 16; r++) {
            if ((r & M) == 0) {
                int r1 = r | M;
                u64 v0 = a[r], v1 = a[r1];
                u64 s0 = swap2(v0), s1 = swap2(v1);
                a[r]  = fma2(i01, s1, fma2(r01, v1, fma2(i00, s0, mul2(r00, v0))));
                a[r1] = fma2(i11, s1, fma2(r11, v1, fma2(i10, s0, mul2(r10, v0))));
            }
        }
    } else {
        int bit = (lane >> B) & 1;
        u64 ur = bit ? r11 : r00, ui = bit ? i11 : i00;
        u64 vr = bit ? r10 : r01, vi = bit ? i10 : i01;
#pragma unroll
        for (int r = 0; r < 16; r++) {
            u64 p = shfl2<(1 << B)>(a[r]);
            u64 t = fma2(ui, swap2(a[r]), mul2(ur, a[r]));
            a[r] = fma2(vi, swap2(p), fma2(vr, p, t));
        }
    }
}

// Diagonal complex (CE form d0, d1) — zero shuffles.
template<int B>
__device__ __forceinline__ void ap_diag_ce(u64 a[16], int lane,
                                           u64 r0, u64 i0, u64 r1, u64 i1) {
    if constexpr (B >= LB) {
        constexpr int M = 1 << (B - LB);
#pragma unroll
        for (int r = 0; r < 16; r++) {
            u64 rr = (r & M) ? r1 : r0;
            u64 ii = (r & M) ? i1 : i0;
            a[r] = fma2(ii, swap2(a[r]), mul2(rr, a[r]));
        }
    } else {
        int bit = (lane >> B) & 1;
        u64 rr = bit ? r1 : r0, ii = bit ? i1 : i0;
#pragma unroll
        for (int r = 0; r < 16; r++)
            a[r] = fma2(ii, swap2(a[r]), mul2(rr, a[r]));
    }
}

// ------------------------- multi-qubit gates --------------------------------

// Controlled-X: flip bit T where all CM bits set. CM==0 -> plain X.
template<int T, int CM>
__device__ __forceinline__ void g_cx(u64 a[16], int lane) {
    constexpr int CML = CM & ((1 << LB) - 1);
    constexpr int CMR = (CM >> LB) & 15;
    bool lp = ((lane & CML) == CML);
    if constexpr (T < LB) {
#pragma unroll
        for (int r = 0; r < 16; r++) {
            if ((r & CMR) == CMR) {
                u64 p = shfl2<(1 << T)>(a[r]);
                if constexpr (CML == 0) a[r] = p;
                else a[r] = lp ? p : a[r];
            }
        }
    } else {
        constexpr int MT = 1 << (T - LB);
#pragma unroll
        for (int r = 0; r < 16; r++) {
            if (((r & CMR) == CMR) && !(r & MT)) {
                int r1 = r | MT;
                u64 v0 = a[r], v1 = a[r1];
                if constexpr (CML == 0) { a[r] = v1; a[r1] = v0; }
                else { a[r] = lp ? v1 : v0; a[r1] = lp ? v0 : v1; }
            }
        }
    }
}

// CZ on bits BA, BB
template<int BA, int BB>
__device__ __forceinline__ void g_cz(u64 a[16], int lane) {
    bool lp = true;
    if constexpr (BA < LB) lp = lp && (((lane >> BA) & 1) != 0);
    if constexpr (BB < LB) lp = lp && (((lane >> BB) & 1) != 0);
    u64 sg = dup2(lp ? -1.f : 1.f);
#pragma unroll
    for (int r = 0; r < 16; r++) {
        bool rp = true;
        if (BA >= LB) rp = rp && (((r >> (BA - LB)) & 1) != 0);
        if (BB >= LB) rp = rp && (((r >> (BB - LB)) & 1) != 0);
        if (rp) a[r] = mul2(sg, a[r]);
    }
}

// Static prune: no swap possible for this r.
template<int A, int Bb, int C>
__device__ __forceinline__ constexpr bool cswap_possible(int r) {
    bool possible = true;
    if (C >= LB && !((r >> (C - LB)) & 1)) possible = false;
    if (A >= LB && Bb >= LB &&
        (((r >> (A - LB)) & 1) == ((r >> (Bb - LB)) & 1))) possible = false;
    return possible;
}

// Swap condition for element (r, lane).
template<int A, int Bb, int C>
__device__ __forceinline__ bool cswap_cond(int r, int lane, bool lctl) {
    int ba = (A  < LB) ? ((lane >> A)  & 1) : ((r >> (A  - LB)) & 1);
    int bb = (Bb < LB) ? ((lane >> Bb) & 1) : ((r >> (Bb - LB)) & 1);
    bool ctl = (C < LB) ? lctl : (((r >> (C - LB)) & 1) != 0);
    return ctl && (ba != bb);
}

// CSWAP: control C; swap bits A,Bb where they differ. Three static shapes:
//  (1) both swap bits lane bits  -> element-wise shuffle select.
//  (2) one register + one lane   -> closed pairs (r, r|MR), shuffled partners.
//  (3) both register bits        -> pairs are (bitA=1,bitB=0) <-> r^MR:
//      pure register conditional swap (R9 wrongly paired 00<->11 here).
template<int A, int Bb, int C>
__device__ __forceinline__ void g_cswap(u64 a[16], int lane) {
    constexpr int M  = (1 << A) | (1 << Bb);
    constexpr int ML = M & ((1 << LB) - 1);
    constexpr int MR = (M >> LB) & 15;
    bool lctl = true;
    if constexpr (C < LB) lctl = (((lane >> C) & 1) != 0);

    if constexpr (MR == 0) {
        // (1) partner is same r, other lane.
#pragma unroll
        for (int r = 0; r < 16; r++) {
            if (cswap_possible<A, Bb, C>(r)) {
                u64 p = shfl2<ML>(a[r]);
                bool sw = cswap_cond<A, Bb, C>(r, lane, lctl);
                a[r] = sw ? p : a[r];
            }
        }
    } else if constexpr (ML != 0) {
        // (2) closed pairs (r, r|MR); partner value needs lane shuffle.
#pragma unroll
        for (int r = 0; r < 16; r++) {
            if ((r & MR) == 0) {
                int r1 = r | MR;
                constexpr bool chk = true; (void)chk;
                bool pos0 = cswap_possible<A, Bb, C>(r);
                bool pos1 = cswap_possible<A, Bb, C>(r | MR);
                u64 p0s = a[r1], p1s = a[r];     // read both before any write
                if (pos0) {
                    u64 p0 = shfl2<ML>(p0s);
                    bool sw0 = cswap_cond<A, Bb, C>(r, lane, lctl);
                    a[r] = sw0 ? p0 : a[r];
                }
                if (pos1) {
                    u64 p1 = shfl2<ML>(p1s);
                    bool sw1 = cswap_cond<A, Bb, C>(r1, lane, lctl);
                    a[r1] = sw1 ? p1 : a[r1];
                }
            }
        }
    } else {
        // (3) both swap bits register bits; ML == 0, no shuffles.
        constexpr int MA = 1 << (A - LB);
        constexpr int MB = 1 << (Bb - LB);
#pragma unroll
        for (int r = 0; r < 16; r++) {
            if ((r & MA) != 0 && (r & MB) == 0) {   // bitA=1, bitB=0
                int r1 = r ^ MR;                    // bitA=0, bitB=1
                bool ctl = (C < LB) ? lctl : (((r >> (C - LB)) & 1) != 0);
                u64 t0 = a[r], t1 = a[r1];
                a[r]  = ctl ? t1 : t0;
                a[r1] = ctl ? t0 : t1;
            }
        }
    }
}

// ---------------------------------------------------------------------------
// Setup: per (layer,node) A = G2_1q * ROT, classified.
// code bits [0:3) = q1: 0 none,1 diag,2 real,3 cplx,4 ry,5 ry+diag,6 ry+real,7 ry+cplx
// code bits [3:6) = multiq: 0 none, 1 CNOT, 2 CSWAP, 3 TOF, 4 CZ.
// ---------------------------------------------------------------------------
__device__ ulonglong2 g_ce[192];
__device__ ulonglong2 g_raw[96];
__device__ float4 g_realmat[48];
__device__ int g_code_dev[48];
__constant__ int c_code[48];

struct C2 { float re, im; };
__device__ __forceinline__ C2 cxm(C2 a, C2 b) {
    C2 o; o.re = a.re * b.re - a.im * b.im; o.im = a.re * b.im + a.im * b.re; return o;
}
__device__ __forceinline__ C2 cxa(C2 a, C2 b) { C2 o; o.re = a.re + b.re; o.im = a.im + b.im; return o; }

__global__ void setup_kernel(const float* __restrict__ qp,
                             const int* __restrict__ dry,
                             const int* __restrict__ drot,
                             const int* __restrict__ dg2) {
    int i = threadIdx.x;
    if (i >= 48) return;
    int layer = i >> 3, node = i & 7;
    int di = layer * 4 + (node & 3);
    float s, c;
    __sincosf(0.5f * qp[i], &s, &c);

    C2 A[2][2] = {{{1.f,0.f},{0.f,0.f}},{{0.f,0.f},{1.f,0.f}}};
    bool haveA = false;
    int rot = drot[di];
    if (rot == 0) {
        A[0][0] = {c,0.f}; A[0][1] = {0.f,-s}; A[1][0] = {0.f,-s}; A[1][1] = {c,0.f};
        haveA = true;
    } else if (rot == 1) {
        A[0][0] = {c,0.f}; A[0][1] = {-s,0.f}; A[1][0] = {s,0.f};  A[1][1] = {c,0.f};
        haveA = true;
    } else if (rot == 2) {
        A[0][0] = {c,-s};  A[0][1] = {0.f,0.f}; A[1][0] = {0.f,0.f}; A[1][1] = {c,s};
        haveA = true;
    }
    int g2 = dg2[di];
    if (g2 >= 1 && g2 <= 4) {
        const float rh = 0.70710678118654752440f;
        C2 G[2][2];
        if (g2 == 1) {
            G[0][0] = {rh,0.f}; G[0][1] = {rh,0.f}; G[1][0] = {rh,0.f}; G[1][1] = {-rh,0.f};
        } else if (g2 == 2) {
            G[0][0] = {0.f,0.f}; G[0][1] = {1.f,0.f}; G[1][0] = {1.f,0.f}; G[1][1] = {0.f,0.f};
        } else if (g2 == 3) {
            G[0][0] = {0.f,0.f}; G[0][1] = {0.f,-1.f}; G[1][0] = {0.f,1.f}; G[1][1] = {0.f,0.f};
        } else {
            G[0][0] = {1.f,0.f}; G[0][1] = {0.f,0.f}; G[1][0] = {0.f,0.f}; G[1][1] = {-1.f,0.f};
        }
        C2 R[2][2];
        for (int r = 0; r < 2; r++)
            for (int cc = 0; cc < 2; cc++)
                R[r][cc] = cxa(cxm(G[r][0], A[0][cc]), cxm(G[r][1], A[1][cc]));
        A[0][0] = R[0][0]; A[0][1] = R[0][1]; A[1][0] = R[1][0]; A[1][1] = R[1][1];
        haveA = true;
    }
    int atype = 0;
    if (haveA) {
        bool offd  = (A[0][1].re != 0.f) || (A[0][1].im != 0.f) ||
                     (A[1][0].re != 0.f) || (A[1][0].im != 0.f);
        bool anyim = (A[0][0].im != 0.f) || (A[0][1].im != 0.f) ||
                     (A[1][0].im != 0.f) || (A[1][1].im != 0.f);
        atype = offd ? (anyim ? 3 : 2) : 1;
    }
    int q1 = (dry[di] & 1) ? (4 + atype) : atype;
    int mq = (g2 >= 5) ? (g2 - 4) : 0;
    g_code_dev[i] = q1 | (mq << 3);

    g_raw[2 * i]     = make_ulonglong2(pack2(A[0][0].re, A[0][0].im),
                                       pack2(A[0][1].re, A[0][1].im));
    g_raw[2 * i + 1] = make_ulonglong2(pack2(A[1][0].re, A[1][0].im),
                                       pack2(A[1][1].re, A[1][1].im));
    g_ce[4 * i + 0] = make_ulonglong2(dup2(A[0][0].re), pack2(-A[0][0].im, A[0][0].im));
    g_ce[4 * i + 1] = make_ulonglong2(dup2(A[0][1].re), pack2(-A[0][1].im, A[0][1].im));
    g_ce[4 * i + 2] = make_ulonglong2(dup2(A[1][0].re), pack2(-A[1][0].im, A[1][0].im));
    g_ce[4 * i + 3] = make_ulonglong2(dup2(A[1][1].re), pack2(-A[1][1].im, A[1][1].im));
    g_realmat[i] = make_float4(A[0][0].re, A[0][1].re, A[1][0].re, A[1][1].re);
}

// ---------------------------------------------------------------------------

template<int NODE>
__device__ __forceinline__ void do_node(u64 a[16], int lane, int layer,
                                        float fc_, float fs_) {
    constexpr int B  = 7 - NODE;
    constexpr int B1 = 7 - ((NODE + 1) & 7);
    constexpr int B2 = 7 - ((NODE + 2) & 7);
    const int idx = layer * 8 + NODE;

    int code = c_code[idx];           // constant -> provably uniform
    int q1 = code & 7;
    if (q1) {
        switch (q1) {
            case 1: {
                ulonglong2 e0 = __ldg(&g_ce[4 * idx]);
                ulonglong2 e3 = __ldg(&g_ce[4 * idx + 3]);
                ap_diag_ce<B>(a, lane, e0.x, e0.y, e3.x, e3.y);
            } break;
            case 2: {
                float4 m = __ldg(&g_realmat[idx]);
                ap_real<B>(a, lane, m.x, m.y, m.z, m.w);
            } break;
            case 3: {
                ulonglong2 e0 = __ldg(&g_ce[4 * idx + 0]);
                ulonglong2 e1 = __ldg(&g_ce[4 * idx + 1]);
                ulonglong2 e2 = __ldg(&g_ce[4 * idx + 2]);
                ulonglong2 e3 = __ldg(&g_ce[4 * idx + 3]);
                ap_cplx_ce<B>(a, lane, e0.x, e0.y, e1.x, e1.y,
                                       e2.x, e2.y, e3.x, e3.y);
            } break;
            case 4: {  // pure RY — width-16 broadcast picks this half-warp's sample
                float c = __shfl_sync(FULLMASK, fc_, NODE, 16);
                float s = __shfl_sync(FULLMASK, fs_, NODE, 16);
                ap_real<B>(a, lane, c, -s, s, c);
            } break;
            case 6: {  // RY folded into real A
                float c = __shfl_sync(FULLMASK, fc_, NODE, 16);
                float s = __shfl_sync(FULLMASK, fs_, NODE, 16);
                float4 m = __ldg(&g_realmat[idx]);
                float u00 = fmaf(m.x, c,  m.y * s);
                float u01 = fmaf(m.y, c, -m.x * s);
                float u10 = fmaf(m.z, c,  m.w * s);
                float u11 = fmaf(m.w, c, -m.z * s);
                ap_real<B>(a, lane, u00, u01, u10, u11);
            } break;
            default: {  // 5 or 7: RY folded into complex A
                float c = __shfl_sync(FULLMASK, fc_, NODE, 16);
                float s = __shfl_sync(FULLMASK, fs_, NODE, 16);
                ulonglong2 ra = __ldg(&g_raw[2 * idx]);
                ulonglong2 rb = __ldg(&g_raw[2 * idx + 1]);
                u64 c2 = dup2(c), s2 = dup2(s), ns2 = dup2(-s);
                u64 M00 = fma2(s2, ra.y, mul2(c2,  ra.x));
                u64 M01 = fma2(c2, ra.y, mul2(ns2, ra.x));
                u64 M10 = fma2(s2, rb.y, mul2(c2,  rb.x));
                u64 M11 = fma2(c2, rb.y, mul2(ns2, rb.x));
                float mr, mi;
                unpack2(M00, mr, mi); u64 r00 = dup2(mr), i00 = pack2(-mi, mi);
                unpack2(M01, mr, mi); u64 r01 = dup2(mr), i01 = pack2(-mi, mi);
                unpack2(M10, mr, mi); u64 r10 = dup2(mr), i10 = pack2(-mi, mi);
                unpack2(M11, mr, mi); u64 r11 = dup2(mr), i11 = pack2(-mi, mi);
                ap_cplx_ce<B>(a, lane, r00, i00, r01, i01, r10, i10, r11, i11);
            } break;
        }
    }
    int mq = (code >> 3) & 7;
    if (mq) {
        switch (mq) {
            case 1: g_cx<B1, (1 << B)>(a, lane); break;               // CNOT
            case 2: g_cswap<B1, B2, B>(a, lane); break;               // CSWAP
            case 3: g_cx<B2, (1 << B) | (1 << B1)>(a, lane); break;   // Toffoli
            default: g_cz<B, B1>(a, lane); break;                     // CZ
        }
    }
}

__global__ void __launch_bounds__(256, 4) qsim_kernel(
    const float* __restrict__ feats,   // [B, 8]
    float* __restrict__ out,           // [B, 8]
    int nwarps) {
    int w = (int)((blockIdx.x * blockDim.x + threadIdx.x) >> 5);
    int lane = threadIdx.x & 31;
    if (w >= nwarps) return;

    int sample = 2 * w + (lane >> 4);       // half-warp's sample
    float fv = feats[sample * 8 + (lane & 7)];
    float fs_, fc_;
    __sincosf(0.5f * fv, &fs_, &fc_);

    // H^8 |0...0>  ==  uniform 1/16 real amplitude
    u64 a[16];
    u64 init = pack2(0.0625f, 0.0f);
#pragma unroll
    for (int r = 0; r < 16; r++) a[r] = init;

#pragma unroll 1
    for (int layer = 0; layer < 6; ++layer) {
        do_node<0>(a, lane, layer, fc_, fs_);
        do_node<1>(a, lane, layer, fc_, fs_);
        do_node<2>(a, lane, layer, fc_, fs_);
        do_node<3>(a, lane, layer, fc_, fs_);
        do_node<4>(a, lane, layer, fc_, fs_);
        do_node<5>(a, lane, layer, fc_, fs_);
        do_node<6>(a, lane, layer, fc_, fs_);
        do_node<7>(a, lane, layer, fc_, fs_);
    }

    // <Z_p> = sum_i |a_i|^2 * (1 - 2*bit_{7-p}(i)),  i = (r<<4) | (lane&15)
    float acc[8];
#pragma unroll
    for (int p = 0; p < 8; p++) acc[p] = 0.f;
    float sgl[8];
#pragma unroll
    for (int p = 4; p < 8; p++)
        sgl[p] = ((lane >> (7 - p)) & 1) ? -1.f : 1.f;   // lane bits 3..0
#pragma unroll
    for (int r = 0; r < 16; r++) {
        float re, im;
        unpack2(a[r], re, im);
        float pr = fmaf(re, re, im * im);
        // p=0..3 -> bits 7..4 -> r bits 3..0: compile-time signs
        acc[0] += ((r >> 3) & 1) ? -pr : pr;
        acc[1] += ((r >> 2) & 1) ? -pr : pr;
        acc[2] += ((r >> 1) & 1) ? -pr : pr;
        acc[3] += (r & 1)        ? -pr : pr;
#pragma unroll
        for (int p = 4; p < 8; p++) acc[p] += sgl[p] * pr;
    }
#pragma unroll
    for (int p = 0; p < 8; p++) {
#pragma unroll
        for (int off = 8; off; off >>= 1)   // width-16 butterfly
            acc[p] += __shfl_xor_sync(FULLMASK, acc[p], off);
    }
    if ((lane & 15) == 0) {
        float4* o = reinterpret_cast<float4*>(out + (size_t)sample * 8);
        o[0] = make_float4(acc[0], acc[1], acc[2], acc[3]);
        o[1] = make_float4(acc[4], acc[5], acc[6], acc[7]);
    }
}

extern "C" void kernel_launch(void* const* d_in, const int* in_sizes, int n_in,
                              void* d_out, int out_size) {
    const float* feats = (const float*)d_in[0];   // [B, 8] float32
    const float* qp    = (const float*)d_in[1];   // [48]  float32
    const int* dry     = (const int*)d_in[2];     // [6,4] int32
    const int* drot    = (const int*)d_in[3];     // [6,4] int32
    const int* dg2     = (const int*)d_in[4];     // [6,4] int32
    float* out         = (float*)d_out;           // [B, 8] float32

    int batch = in_sizes[0] / 8;
    int nwarps = batch / 2;                       // 2 samples per warp

    setup_kernel<<<1, 64>>>(qp, dry, drot, dg2);

    void* code_src = nullptr;
    cudaGetSymbolAddress(&code_src, g_code_dev);
    cudaMemcpyToSymbolAsync(c_code, code_src, 48 * sizeof(int), 0,
                            cudaMemcpyDeviceToDevice);

    int threads = 256;
    long long total_threads = (long long)nwarps * 32;
    int blocks = (int)((total_threads + threads - 1) / threads);
    qsim_kernel<<<blocks, threads>>>(feats, out, nwarps);
}